// round 6
// baseline (speedup 1.0000x reference)
#include <cuda_runtime.h>
#include <cuda_bf16.h>
#include <cstdint>

#define B 16
#define S 200
#define D 256
#define H 8
#define W 32
#define RS 0.17677669529663689f   // 1/sqrt(32)
#define CHUNK 8                   // j-rows per smem chunk
#define NCHUNK (S / CHUNK)        // 25

// ---------------- scratch (no allocations allowed) ----------------
__device__ float g_q[B * S * D];
__device__ float g_k[B * S * D];
__device__ float g_v[B * S * D];

// ---------------- tf32 helpers ----------------
__device__ __forceinline__ uint32_t tf32_hi_bits(float a) {
    return __float_as_uint(a) & 0xffffe000u;
}

__device__ __forceinline__ void mma_tf32(
    float& c0, float& c1, float& c2, float& c3,
    uint32_t a0, uint32_t a1, uint32_t a2, uint32_t a3,
    uint32_t b0, uint32_t b1)
{
    asm volatile(
        "mma.sync.aligned.m16n8k8.row.col.f32.tf32.tf32.f32 "
        "{%0,%1,%2,%3}, {%4,%5,%6,%7}, {%8,%9}, {%0,%1,%2,%3};"
        : "+f"(c0), "+f"(c1), "+f"(c2), "+f"(c3)
        : "r"(a0), "r"(a1), "r"(a2), "r"(a3), "r"(b0), "r"(b1));
}

// ---------------- cp.async helpers ----------------
__device__ __forceinline__ void cp_async16(uint32_t dst, const void* src) {
    asm volatile("cp.async.cg.shared.global [%0], [%1], 16;" :: "r"(dst), "l"(src));
}
#define CP_COMMIT() asm volatile("cp.async.commit_group;" ::: "memory")
#define CP_WAIT1()  asm volatile("cp.async.wait_group 1;" ::: "memory")

// copy one 8KB chunk (8 rows x 1KB) into smem; 2 x 16B per thread (256 thr)
__device__ __forceinline__ void prefetch_chunk(const float* gsrc, float* sdst, int tid) {
    uint32_t d = (uint32_t)__cvta_generic_to_shared(sdst);
    cp_async16(d + tid * 16,        gsrc + tid * 4);
    cp_async16(d + tid * 16 + 4096, gsrc + tid * 4 + 1024);
    CP_COMMIT();
}

// ---------------- kernel 1: tf32 tensor-core projection ----------------
// 128 threads, 32x64 tile -> 1200 blocks (finer waves than 600x256).
#define PTM 32
#define PTN 64
#define PTK 32

__global__ __launch_bounds__(128) void proj_tc_kernel(
    const float* __restrict__ x,
    const float* __restrict__ Wq, const float* __restrict__ bq,
    const float* __restrict__ Wk, const float* __restrict__ bk,
    const float* __restrict__ Wv, const float* __restrict__ bv)
{
    __shared__ float sa[PTM][PTK + 4];   // x tile [m][k]
    __shared__ float sb[PTN][PTK + 4];   // W tile [n][k]

    const int tid  = threadIdx.x;
    const int lane = tid & 31;
    const int wid  = tid >> 5;           // 0..3: warp over N
    const int m0   = blockIdx.x * PTM;
    const int mat  = blockIdx.y >> 2;    // 0=q,1=k,2=v
    const int nc0  = (blockIdx.y & 3) * PTN;

    const float* Wm   = (mat == 0) ? Wq : (mat == 1) ? Wk : Wv;
    const float* bias = (mat == 0) ? bq : (mat == 1) ? bk : bv;
    float* dst        = (mat == 0) ? g_q : (mat == 1) ? g_k : g_v;

    const int wn0 = wid * 16;
    const int g   = lane >> 2;
    const int tg  = lane & 3;

    float c[2][2][4];
    #pragma unroll
    for (int i = 0; i < 2; i++)
        #pragma unroll
        for (int j = 0; j < 2; j++)
            #pragma unroll
            for (int r = 0; r < 4; r++) c[i][j][r] = 0.f;

    const int xrow = tid >> 2;           // 0..31
    const int xk   = (tid & 3) * 8;      // 0,8,16,24
    const int wrow = tid >> 1;           // 0..63
    const int wk2  = (tid & 1) * 16;     // 0,16

    for (int k0 = 0; k0 < D; k0 += PTK) {
        float4 xa = *(const float4*)&x[(m0 + xrow) * D + k0 + xk];
        float4 xb = *(const float4*)&x[(m0 + xrow) * D + k0 + xk + 4];
        *(float4*)&sa[xrow][xk]     = xa;
        *(float4*)&sa[xrow][xk + 4] = xb;
        #pragma unroll
        for (int q4 = 0; q4 < 4; q4++) {
            float4 wv4 = *(const float4*)&Wm[(nc0 + wrow) * D + k0 + wk2 + q4 * 4];
            *(float4*)&sb[wrow][wk2 + q4 * 4] = wv4;
        }
        __syncthreads();

        #pragma unroll
        for (int kk = 0; kk < 4; kk++) {
            const int kc = kk * 8;
            float af[2][4];
            #pragma unroll
            for (int i = 0; i < 2; i++) {
                const int rbase = 16 * i + g;
                af[i][0] = sa[rbase    ][kc + tg];
                af[i][1] = sa[rbase + 8][kc + tg];
                af[i][2] = sa[rbase    ][kc + tg + 4];
                af[i][3] = sa[rbase + 8][kc + tg + 4];
            }
            float bf[2][2];
            #pragma unroll
            for (int j = 0; j < 2; j++) {
                const int cbase = wn0 + 8 * j + g;
                bf[j][0] = sb[cbase][kc + tg];
                bf[j][1] = sb[cbase][kc + tg + 4];
            }
            uint32_t ah[2][4], al[2][4], bh[2][2], bl[2][2];
            #pragma unroll
            for (int i = 0; i < 2; i++)
                #pragma unroll
                for (int r = 0; r < 4; r++) {
                    uint32_t hb = tf32_hi_bits(af[i][r]);
                    ah[i][r] = hb;
                    float lo = af[i][r] - __uint_as_float(hb);
                    al[i][r] = tf32_hi_bits(lo);
                }
            #pragma unroll
            for (int j = 0; j < 2; j++)
                #pragma unroll
                for (int r = 0; r < 2; r++) {
                    uint32_t hb = tf32_hi_bits(bf[j][r]);
                    bh[j][r] = hb;
                    float lo = bf[j][r] - __uint_as_float(hb);
                    bl[j][r] = tf32_hi_bits(lo);
                }
            #pragma unroll
            for (int i = 0; i < 2; i++)
                #pragma unroll
                for (int j = 0; j < 2; j++) {
                    mma_tf32(c[i][j][0], c[i][j][1], c[i][j][2], c[i][j][3],
                             ah[i][0], ah[i][1], ah[i][2], ah[i][3],
                             bh[j][0], bh[j][1]);
                    mma_tf32(c[i][j][0], c[i][j][1], c[i][j][2], c[i][j][3],
                             al[i][0], al[i][1], al[i][2], al[i][3],
                             bh[j][0], bh[j][1]);
                    mma_tf32(c[i][j][0], c[i][j][1], c[i][j][2], c[i][j][3],
                             ah[i][0], ah[i][1], ah[i][2], ah[i][3],
                             bl[j][0], bl[j][1]);
                }
        }
        __syncthreads();
    }

    #pragma unroll
    for (int i = 0; i < 2; i++) {
        const int r0 = m0 + 16 * i + g;
        #pragma unroll
        for (int j = 0; j < 2; j++) {
            const int cg = nc0 + wn0 + 8 * j + tg * 2;
            const float b0v = bias[cg], b1v = bias[cg + 1];
            float2 v0 = make_float2(c[i][j][0] + b0v, c[i][j][1] + b1v);
            float2 v1 = make_float2(c[i][j][2] + b0v, c[i][j][3] + b1v);
            *(float2*)&dst[(size_t)r0 * D + cg]       = v0;
            *(float2*)&dst[(size_t)(r0 + 8) * D + cg] = v1;
        }
    }
}

// ---------------- kernel 2: fused attention with cp.async pipeline ----------------
// Block per (b,i). t_K / t_V stream through a 2x8KB smem double buffer.
__global__ __launch_bounds__(256) void fused_attn_kernel(
    const float* __restrict__ tK, const float* __restrict__ tV,
    const int* __restrict__ mask, float* __restrict__ out)
{
    __shared__ float tbuf[2][CHUNK][D];   // 16 KB double buffer
    __shared__ float sp[H][S];            // scores -> probs, 6.4 KB
    __shared__ float4 pbuf[4][64];        // phase-C partials, 4 KB

    const int bi   = blockIdx.x;
    const int b    = bi / S;
    const int tid  = threadIdx.x;
    const int warp = tid >> 5;
    const int lane = tid & 31;

    const float* tKbase = tK + (size_t)bi * S * D;
    const float* tVbase = tV + (size_t)bi * S * D;

    // prime the pipeline: t_K chunks 0 and 1
    prefetch_chunk(tKbase,             &tbuf[0][0][0], tid);
    prefetch_chunk(tKbase + CHUNK * D, &tbuf[1][0][0], tid);

    // ---- Phase A: scores[h][j] = sum_d q[i,d]*(tK[i,j,d]+k[j,d]) ----
    {
        const float* qrow = g_q + (size_t)bi * D + lane * 8;
        const float4 qa = *(const float4*)(qrow);
        const float4 qb = *(const float4*)(qrow + 4);

        for (int c = 0; c < NCHUNK; c++) {
            const int j = c * CHUNK + warp;           // one j-row per warp
            const float* kp = g_k + (size_t)(b * S + j) * D + lane * 8;
            // issue k loads before the wait so L2 latency hides behind it
            float4 k0 = *(const float4*)(kp);
            float4 k1 = *(const float4*)(kp + 4);

            CP_WAIT1();
            __syncthreads();

            const float* trow = &tbuf[c & 1][warp][lane * 8];
            float4 t0 = *(const float4*)(trow);
            float4 t1 = *(const float4*)(trow + 4);

            float p = qa.x * (t0.x + k0.x) + qa.y * (t0.y + k0.y)
                    + qa.z * (t0.z + k0.z) + qa.w * (t0.w + k0.w)
                    + qb.x * (t1.x + k1.x) + qb.y * (t1.y + k1.y)
                    + qb.z * (t1.z + k1.z) + qb.w * (t1.w + k1.w);

            p += __shfl_xor_sync(0xFFFFFFFFu, p, 1);
            p += __shfl_xor_sync(0xFFFFFFFFu, p, 2);
            if ((lane & 3) == 0) sp[lane >> 2][j] = p;

            __syncthreads();

            // refill the buffer just consumed; tail switches to t_V so the
            // softmax bubble is bridged by in-flight DRAM traffic
            if (c + 2 < NCHUNK)
                prefetch_chunk(tKbase + (size_t)(c + 2) * CHUNK * D, &tbuf[c & 1][0][0], tid);
            else if (c + 2 == NCHUNK)
                prefetch_chunk(tVbase,             &tbuf[c & 1][0][0], tid);  // tV chunk 0
            else
                prefetch_chunk(tVbase + CHUNK * D, &tbuf[c & 1][0][0], tid);  // tV chunk 1
        }
    }

    // ---- Phase B: per-head softmax (warp h handles head h) ----
    {
        float vals[7];
        float mx = -1e30f;
        #pragma unroll
        for (int t = 0; t < 7; t++) {
            int j = lane + t * 32;
            if (j < S) {
                float mb = 10000.0f * (1.0f - (float)mask[b * S + j]);
                vals[t] = sp[warp][j] * RS + mb;
            } else {
                vals[t] = -1e30f;
            }
            mx = fmaxf(mx, vals[t]);
        }
        #pragma unroll
        for (int o = 16; o; o >>= 1) mx = fmaxf(mx, __shfl_xor_sync(0xFFFFFFFFu, mx, o));

        float sum = 0.f;
        #pragma unroll
        for (int t = 0; t < 7; t++) {
            vals[t] = __expf(vals[t] - mx);
            sum += vals[t];
        }
        #pragma unroll
        for (int o = 16; o; o >>= 1) sum += __shfl_xor_sync(0xFFFFFFFFu, sum, o);

        const float inv = 1.0f / sum;
        #pragma unroll
        for (int t = 0; t < 7; t++) {
            int j = lane + t * 32;
            if (j < S) sp[warp][j] = vals[t] * inv;
        }
    }
    __syncthreads();   // sp final before Phase C reads

    // ---- Phase C: out[d] = sum_j p[h(d)][j]*(tV[i,j,d]+v[j,d]) ----
    // tV chunk c sits in tbuf[(c+1)&1] (chunk0 landed in buf1, chunk1 in buf0).
    {
        const int jsub = tid >> 6;        // 0..3: local row pair within chunk
        const int l    = tid & 63;        // d-slice
        const int d    = l * 4;
        const int h    = l >> 3;

        float4 acc = make_float4(0.f, 0.f, 0.f, 0.f);

        for (int c = 0; c < NCHUNK; c++) {
            const int r0 = jsub * 2;
            const int j0 = c * CHUNK + r0;
            const float* vp0 = g_v + (size_t)(b * S + j0) * D + d;
            float4 vv0 = *(const float4*)(vp0);
            float4 vv1 = *(const float4*)(vp0 + D);

            CP_WAIT1();
            __syncthreads();

            const int s = (c + 1) & 1;
            float4 tv0 = *(const float4*)&tbuf[s][r0][d];
            float4 tv1 = *(const float4*)&tbuf[s][r0 + 1][d];
            float p0 = sp[h][j0];
            float p1 = sp[h][j0 + 1];

            acc.x += p0 * (tv0.x + vv0.x) + p1 * (tv1.x + vv1.x);
            acc.y += p0 * (tv0.y + vv0.y) + p1 * (tv1.y + vv1.y);
            acc.z += p0 * (tv0.z + vv0.z) + p1 * (tv1.z + vv1.z);
            acc.w += p0 * (tv0.w + vv0.w) + p1 * (tv1.w + vv1.w);

            __syncthreads();

            if (c + 2 < NCHUNK)
                prefetch_chunk(tVbase + (size_t)(c + 2) * CHUNK * D, &tbuf[s][0][0], tid);
            else
                CP_COMMIT();   // empty group keeps the wait_group count aligned
        }

        pbuf[jsub][l] = acc;
    }
    __syncthreads();

    if (tid < 64) {
        const int l = tid;
        float4 a0 = pbuf[0][l], a1 = pbuf[1][l], a2 = pbuf[2][l], a3 = pbuf[3][l];
        float4 r;
        r.x = (a0.x + a1.x) + (a2.x + a3.x);
        r.y = (a0.y + a1.y) + (a2.y + a3.y);
        r.z = (a0.z + a1.z) + (a2.z + a3.z);
        r.w = (a0.w + a1.w) + (a2.w + a3.w);
        *(float4*)(out + (size_t)bi * D + l * 4) = r;
    }
}

// ---------------- launch ----------------
extern "C" void kernel_launch(void* const* d_in, const int* in_sizes, int n_in,
                              void* d_out, int out_size)
{
    const float* x    = (const float*)d_in[0];
    const float* tK   = (const float*)d_in[1];
    const float* tV   = (const float*)d_in[2];
    const int*   mask = (const int*)  d_in[3];
    const float* Wq   = (const float*)d_in[4];
    const float* bq   = (const float*)d_in[5];
    const float* Wk   = (const float*)d_in[6];
    const float* bk   = (const float*)d_in[7];
    const float* Wv   = (const float*)d_in[8];
    const float* bv   = (const float*)d_in[9];
    float* out = (float*)d_out;

    dim3 pgrid(B * S / PTM, 12);   // 100 x 12 = 1200 blocks, 128 threads
    proj_tc_kernel<<<pgrid, 128>>>(x, Wq, bq, Wk, bk, Wv, bv);

    fused_attn_kernel<<<B * S, 256>>>(tK, tV, mask, out);
}

// round 7
// speedup vs baseline: 1.0940x; 1.0940x over previous
#include <cuda_runtime.h>
#include <cuda_bf16.h>
#include <cstdint>

#define B 16
#define S 200
#define D 256
#define H 8
#define W 32
#define RS 0.17677669529663689f   // 1/sqrt(32)

// ---------------- scratch (no allocations allowed) ----------------
__device__ float g_q[B * S * D];
__device__ float g_k[B * S * D];
__device__ float g_v[B * S * D];

// ---------------- tf32 helpers ----------------
__device__ __forceinline__ uint32_t tf32_hi_bits(float a) {
    return __float_as_uint(a) & 0xffffe000u;
}

__device__ __forceinline__ void mma_tf32(
    float& c0, float& c1, float& c2, float& c3,
    uint32_t a0, uint32_t a1, uint32_t a2, uint32_t a3,
    uint32_t b0, uint32_t b1)
{
    asm volatile(
        "mma.sync.aligned.m16n8k8.row.col.f32.tf32.tf32.f32 "
        "{%0,%1,%2,%3}, {%4,%5,%6,%7}, {%8,%9}, {%0,%1,%2,%3};"
        : "+f"(c0), "+f"(c1), "+f"(c2), "+f"(c3)
        : "r"(a0), "r"(a1), "r"(a2), "r"(a3), "r"(b0), "r"(b1));
}

// ---------------- cp.async helpers (proj only) ----------------
__device__ __forceinline__ void cp_async16(uint32_t dst, const void* src) {
    asm volatile("cp.async.cg.shared.global [%0], [%1], 16;" :: "r"(dst), "l"(src));
}
#define CP_COMMIT() asm volatile("cp.async.commit_group;" ::: "memory")
#define CP_WAIT1()  asm volatile("cp.async.wait_group 1;" ::: "memory")

// ---------------- kernel 1: tf32 TC projection, cp.async double-buffered ----------------
#define PTM 64
#define PTN 64
#define PTK 32
#define PPAD 4

__global__ __launch_bounds__(256) void proj_tc_kernel(
    const float* __restrict__ x,
    const float* __restrict__ Wq, const float* __restrict__ bq,
    const float* __restrict__ Wk, const float* __restrict__ bk,
    const float* __restrict__ Wv, const float* __restrict__ bv)
{
    __shared__ float sa[2][PTM][PTK + PPAD];   // x tiles,  2 x 9.2 KB
    __shared__ float sb[2][PTN][PTK + PPAD];   // W tiles,  2 x 9.2 KB

    const int tid  = threadIdx.x;
    const int lane = tid & 31;
    const int wid  = tid >> 5;
    const int m0   = blockIdx.x * PTM;
    const int mat  = blockIdx.y >> 2;             // 0=q,1=k,2=v
    const int nc0  = (blockIdx.y & 3) * PTN;

    const float* Wm   = (mat == 0) ? Wq : (mat == 1) ? Wk : Wv;
    const float* bias = (mat == 0) ? bq : (mat == 1) ? bk : bv;
    float* dst        = (mat == 0) ? g_q : (mat == 1) ? g_k : g_v;

    const int warp_m = wid & 1;
    const int warp_n = wid >> 1;
    const int wm0 = warp_m * 32;
    const int wn0 = warp_n * 16;

    const int g  = lane >> 2;
    const int tg = lane & 3;

    const int lrow = tid >> 2;            // 0..63
    const int lk   = (tid & 3) * 8;       // 0,8,16,24

    // per-thread prefetch of one K-tile into buffer `s`
    const float* xsrc = x  + (size_t)(m0  + lrow) * D + lk;
    const float* wsrc = Wm + (size_t)(nc0 + lrow) * D + lk;
    uint32_t sa_dst = (uint32_t)__cvta_generic_to_shared(&sa[0][lrow][lk]);
    uint32_t sb_dst = (uint32_t)__cvta_generic_to_shared(&sb[0][lrow][lk]);
    const uint32_t bufstride = (uint32_t)(PTM * (PTK + PPAD) * 4);

    #define PROJ_PREFETCH(t, s)                                        \
        do {                                                           \
            cp_async16(sa_dst + (s) * bufstride,      xsrc + (t) * PTK);      \
            cp_async16(sa_dst + (s) * bufstride + 16, xsrc + (t) * PTK + 4);  \
            cp_async16(sb_dst + (s) * bufstride,      wsrc + (t) * PTK);      \
            cp_async16(sb_dst + (s) * bufstride + 16, wsrc + (t) * PTK + 4);  \
            CP_COMMIT();                                               \
        } while (0)

    float c[2][2][4];
    #pragma unroll
    for (int i = 0; i < 2; i++)
        #pragma unroll
        for (int j = 0; j < 2; j++)
            #pragma unroll
            for (int r = 0; r < 4; r++) c[i][j][r] = 0.f;

    PROJ_PREFETCH(0, 0);

    #pragma unroll 1
    for (int t = 0; t < D / PTK; t++) {
        if (t + 1 < D / PTK) PROJ_PREFETCH(t + 1, (t + 1) & 1);
        else                 CP_COMMIT();          // empty group keeps count aligned
        CP_WAIT1();
        __syncthreads();

        const int s = t & 1;
        #pragma unroll
        for (int kk = 0; kk < 4; kk++) {
            const int kc = kk * 8;
            float af[2][4];
            #pragma unroll
            for (int i = 0; i < 2; i++) {
                const int rbase = wm0 + 16 * i + g;
                af[i][0] = sa[s][rbase    ][kc + tg];
                af[i][1] = sa[s][rbase + 8][kc + tg];
                af[i][2] = sa[s][rbase    ][kc + tg + 4];
                af[i][3] = sa[s][rbase + 8][kc + tg + 4];
            }
            float bf[2][2];
            #pragma unroll
            for (int j = 0; j < 2; j++) {
                const int cbase = wn0 + 8 * j + g;
                bf[j][0] = sb[s][cbase][kc + tg];
                bf[j][1] = sb[s][cbase][kc + tg + 4];
            }
            uint32_t ah[2][4], al[2][4], bh[2][2], bl[2][2];
            #pragma unroll
            for (int i = 0; i < 2; i++)
                #pragma unroll
                for (int r = 0; r < 4; r++) {
                    uint32_t hb = tf32_hi_bits(af[i][r]);
                    ah[i][r] = hb;
                    float lo = af[i][r] - __uint_as_float(hb);
                    al[i][r] = tf32_hi_bits(lo);
                }
            #pragma unroll
            for (int j = 0; j < 2; j++)
                #pragma unroll
                for (int r = 0; r < 2; r++) {
                    uint32_t hb = tf32_hi_bits(bf[j][r]);
                    bh[j][r] = hb;
                    float lo = bf[j][r] - __uint_as_float(hb);
                    bl[j][r] = tf32_hi_bits(lo);
                }
            #pragma unroll
            for (int i = 0; i < 2; i++)
                #pragma unroll
                for (int j = 0; j < 2; j++) {
                    mma_tf32(c[i][j][0], c[i][j][1], c[i][j][2], c[i][j][3],
                             ah[i][0], ah[i][1], ah[i][2], ah[i][3],
                             bh[j][0], bh[j][1]);
                    mma_tf32(c[i][j][0], c[i][j][1], c[i][j][2], c[i][j][3],
                             al[i][0], al[i][1], al[i][2], al[i][3],
                             bh[j][0], bh[j][1]);
                    mma_tf32(c[i][j][0], c[i][j][1], c[i][j][2], c[i][j][3],
                             ah[i][0], ah[i][1], ah[i][2], ah[i][3],
                             bl[j][0], bl[j][1]);
                }
        }
        __syncthreads();   // buffer t&1 free before prefetch t+2 writes it
    }

    #pragma unroll
    for (int i = 0; i < 2; i++) {
        const int r0 = m0 + wm0 + 16 * i + g;
        #pragma unroll
        for (int j = 0; j < 2; j++) {
            const int cg = nc0 + wn0 + 8 * j + tg * 2;
            const float b0v = bias[cg], b1v = bias[cg + 1];
            float2 v0 = make_float2(c[i][j][0] + b0v, c[i][j][1] + b1v);
            float2 v1 = make_float2(c[i][j][2] + b0v, c[i][j][3] + b1v);
            *(float2*)&dst[(size_t)r0 * D + cg]       = v0;
            *(float2*)&dst[(size_t)(r0 + 8) * D + cg] = v1;
        }
    }
}

// ---------------- kernel 2: fused attention (round-5 exact — best known) ----------------
__global__ __launch_bounds__(256, 6) void fused_attn_kernel(
    const float* __restrict__ tK, const float* __restrict__ tV,
    const int* __restrict__ mask, float* __restrict__ out)
{
    __shared__ float sp[H][S];          // scores -> probs, 6.4 KB
    __shared__ float4 pbuf[4][64];      // phase-C partials, 4 KB

    const int bi = blockIdx.x;          // 0..B*S-1
    const int b  = bi / S;
    const int warp = threadIdx.x >> 5;  // 0..7
    const int lane = threadIdx.x & 31;

    // ---- Phase A: scores[h][j] = sum_d q[i,d]*(tK[i,j,d]+k[j,d]) ----
    {
        const float* qrow = g_q + (size_t)bi * D + lane * 8;
        const float4 qa = *(const float4*)(qrow);
        const float4 qb = *(const float4*)(qrow + 4);

        #pragma unroll 5
        for (int j = warp; j < S; j += 8) {
            const float* tp = tK  + ((size_t)bi * S + j) * D + lane * 8;
            const float* kp = g_k + ((size_t)(b * S + j)) * D + lane * 8;
            float4 t0 = __ldcs((const float4*)(tp));
            float4 t1 = __ldcs((const float4*)(tp + 4));
            float4 k0 = *(const float4*)(kp);
            float4 k1 = *(const float4*)(kp + 4);

            float p = qa.x * (t0.x + k0.x) + qa.y * (t0.y + k0.y)
                    + qa.z * (t0.z + k0.z) + qa.w * (t0.w + k0.w)
                    + qb.x * (t1.x + k1.x) + qb.y * (t1.y + k1.y)
                    + qb.z * (t1.z + k1.z) + qb.w * (t1.w + k1.w);

            p += __shfl_xor_sync(0xFFFFFFFFu, p, 1);
            p += __shfl_xor_sync(0xFFFFFFFFu, p, 2);
            if ((lane & 3) == 0) sp[lane >> 2][j] = p;
        }
    }
    __syncthreads();

    // ---- Phase B: per-head softmax (warp h handles head h) ----
    {
        float vals[7];
        float mx = -1e30f;
        #pragma unroll
        for (int t = 0; t < 7; t++) {
            int j = lane + t * 32;
            if (j < S) {
                float mb = 10000.0f * (1.0f - (float)mask[b * S + j]);
                vals[t] = sp[warp][j] * RS + mb;
            } else {
                vals[t] = -1e30f;
            }
            mx = fmaxf(mx, vals[t]);
        }
        #pragma unroll
        for (int o = 16; o; o >>= 1) mx = fmaxf(mx, __shfl_xor_sync(0xFFFFFFFFu, mx, o));

        float sum = 0.f;
        #pragma unroll
        for (int t = 0; t < 7; t++) {
            vals[t] = __expf(vals[t] - mx);
            sum += vals[t];
        }
        #pragma unroll
        for (int o = 16; o; o >>= 1) sum += __shfl_xor_sync(0xFFFFFFFFu, sum, o);

        const float inv = 1.0f / sum;
        #pragma unroll
        for (int t = 0; t < 7; t++) {
            int j = lane + t * 32;
            if (j < S) sp[warp][j] = vals[t] * inv;
        }
    }
    __syncthreads();

    // ---- Phase C: out[d] = sum_j p[h(d)][j]*(tV[i,j,d]+v[j,d]) ----
    {
        const int g = threadIdx.x >> 6;     // j-group 0..3
        const int l = threadIdx.x & 63;     // d-slice 0..63
        const int d = l * 4;
        const int h = l >> 3;

        const float* tvb = tV  + ((size_t)bi * S) * D + d;
        const float* vvb = g_v + ((size_t)b * S) * D + d;

        float4 acc = make_float4(0.f, 0.f, 0.f, 0.f);
        #pragma unroll 5
        for (int j = g; j < S; j += 4) {
            float4 tv = __ldcs((const float4*)(tvb + (size_t)j * D));
            float4 vv = *(const float4*)(vvb + (size_t)j * D);
            float pj = sp[h][j];
            acc.x += pj * (tv.x + vv.x);
            acc.y += pj * (tv.y + vv.y);
            acc.z += pj * (tv.z + vv.z);
            acc.w += pj * (tv.w + vv.w);
        }
        pbuf[g][l] = acc;
    }
    __syncthreads();

    if (threadIdx.x < 64) {
        const int l = threadIdx.x;
        float4 a0 = pbuf[0][l], a1 = pbuf[1][l], a2 = pbuf[2][l], a3 = pbuf[3][l];
        float4 r;
        r.x = (a0.x + a1.x) + (a2.x + a3.x);
        r.y = (a0.y + a1.y) + (a2.y + a3.y);
        r.z = (a0.z + a1.z) + (a2.z + a3.z);
        r.w = (a0.w + a1.w) + (a2.w + a3.w);
        *(float4*)(out + (size_t)bi * D + l * 4) = r;
    }
}

// ---------------- launch ----------------
extern "C" void kernel_launch(void* const* d_in, const int* in_sizes, int n_in,
                              void* d_out, int out_size)
{
    const float* x    = (const float*)d_in[0];
    const float* tK   = (const float*)d_in[1];
    const float* tV   = (const float*)d_in[2];
    const int*   mask = (const int*)  d_in[3];
    const float* Wq   = (const float*)d_in[4];
    const float* bq   = (const float*)d_in[5];
    const float* Wk   = (const float*)d_in[6];
    const float* bk   = (const float*)d_in[7];
    const float* Wv   = (const float*)d_in[8];
    const float* bv   = (const float*)d_in[9];
    float* out = (float*)d_out;

    dim3 pgrid(B * S / PTM, 12);   // 50 x (3 matrices * 4 col blocks) = 600 blocks
    proj_tc_kernel<<<pgrid, 256>>>(x, Wq, bq, Wk, bk, Wv, bv);

    fused_attn_kernel<<<B * S, 256>>>(tK, tV, mask, out);
}